// round 3
// baseline (speedup 1.0000x reference)
#include <cuda_runtime.h>

#define D16 16
#define H64 64
#define NMASK 32767
#define EPSQ 1e-10f
#define L2E 1.4426950408889634f

#define TPB 128
#define IPT 8
#define BLK_PER_PAIR 32   // 32 blocks * 128 threads * 8 items = 32768 >= 32767
#define NPAIR 16

__device__ unsigned g_min[NPAIR];

static __device__ __forceinline__ unsigned long long pk2(float lo, float hi) {
    unsigned long long r;
    asm("mov.b64 %0, {%1, %2};" : "=l"(r) : "f"(lo), "f"(hi));
    return r;
}
static __device__ __forceinline__ void upk2(unsigned long long v, float& lo, float& hi) {
    asm("mov.b64 {%0, %1}, %2;" : "=f"(lo), "=f"(hi) : "l"(v));
}
static __device__ __forceinline__ unsigned long long ffma2(unsigned long long a,
                                                           unsigned long long b,
                                                           unsigned long long c) {
    unsigned long long d;
    asm("fma.rn.f32x2 %0, %1, %2, %3;" : "=l"(d) : "l"(a), "l"(b), "l"(c));
    return d;
}
static __device__ __forceinline__ float ex2f(float x) {
    float y; asm("ex2.approx.f32 %0, %1;" : "=f"(y) : "f"(x)); return y;
}
static __device__ __forceinline__ float lg2a(float x) {
    float y; asm("lg2.approx.f32 %0, %1;" : "=f"(y) : "f"(x)); return y;
}
static __device__ __forceinline__ float rcpf(float x) {
    float y; asm("rcp.approx.f32 %0, %1;" : "=f"(y) : "f"(x)); return y;
}

// Order-preserving float -> unsigned map (works for negatives too)
static __device__ __forceinline__ unsigned fmap(float f) {
    unsigned b = __float_as_uint(f);
    return (b & 0x80000000u) ? ~b : (b | 0x80000000u);
}
static __device__ __forceinline__ float funmap(unsigned u) {
    unsigned b = (u & 0x80000000u) ? (u ^ 0x80000000u) : ~u;
    return __uint_as_float(b);
}

__global__ void init_kernel() {
    if (threadIdx.x < NPAIR) g_min[threadIdx.x] = 0xFFFFFFFFu;
}

__global__ void finish_kernel(float* __restrict__ out) {
    if (threadIdx.x < NPAIR) out[threadIdx.x] = funmap(g_min[threadIdx.x]);
}

__global__ void __launch_bounds__(TPB, 2)
phi_kernel(const float* __restrict__ state,
           const float* __restrict__ cw1, const float* __restrict__ cb1,
           const float* __restrict__ cw2, const float* __restrict__ cb2,
           const float* __restrict__ ew1, const float* __restrict__ eb1,
           const float* __restrict__ ew2, const float* __restrict__ eb2) {
    __shared__ float acc_sm[H64 * TPB];              // per-thread Gray accumulator
    __shared__ float c_sm[H64 * D16];                // c_sm[h*16+d] = W1[h,d]*state[b,d]
    __shared__ unsigned long long w2p_sm[H64 * D16]; // w2p_sm[h*16+j] = pack(W2[j,h], W2[j,h])
    __shared__ float T_sm[H64];                      // 2*b1 + sum_d c[d]
    __shared__ float b1_sm[H64];
    __shared__ float b2L_sm[D16];                    // b2[j] * log2(e)
    __shared__ float p_sm[D16];
    __shared__ float C_sm;
    __shared__ float hfull_sm[H64];
    __shared__ float wmin_sm[TPB / 32];

    const int pair = blockIdx.x / BLK_PER_PAIR;
    const int cblk = blockIdx.x % BLK_PER_PAIR;
    const int b    = pair & 7;
    const int dir  = pair >> 3;
    const float* __restrict__ w1 = dir ? ew1 : cw1;
    const float* __restrict__ b1 = dir ? eb1 : cb1;
    const float* __restrict__ w2 = dir ? ew2 : cw2;
    const float* __restrict__ b2 = dir ? eb2 : cb2;

    const int tid = threadIdx.x;

    // ---- stage shared tables ----
    for (int idx = tid; idx < H64 * D16; idx += TPB) {
        int h = idx >> 4, d = idx & 15;
        c_sm[idx] = w1[h * D16 + d] * state[b * D16 + d];
        float wv = w2[d * H64 + h];   // d plays the role of output index j: W2[j, h]
        w2p_sm[idx] = pk2(wv, wv);
    }
    if (tid < D16) b2L_sm[tid] = b2[tid] * L2E;
    if (tid < H64) b1_sm[tid] = b1[tid];
    __syncthreads();

    if (tid < H64) {
        float s = 0.f;
        #pragma unroll
        for (int d = 0; d < D16; ++d) s += c_sm[tid * D16 + d];
        float t = 2.f * b1_sm[tid] + s;
        T_sm[tid] = t;
        hfull_sm[tid] = fmaxf(t - b1_sm[tid], 0.f);  // full (unmasked) hidden
    }
    __syncthreads();
    // ---- full-state softmax p, C = sum p*log2(p); warp-cooperative, no arrays ----
    if (tid < 32) {
        float e = 0.f;
        const int j = tid & 15;
        if (tid < D16) {
            float z = b2[j];
            #pragma unroll
            for (int h = 0; h < H64; ++h) z = fmaf(w2[j * H64 + h], hfull_sm[h], z);
            e = ex2f(z * L2E);
        }
        float S = e;
        #pragma unroll
        for (int off = 8; off; off >>= 1) S += __shfl_xor_sync(0xffffffffu, S, off);
        if (tid < D16) {
            float p = fmaxf(e * rcpf(S), EPSQ);
            p_sm[j] = p;
            float cpart = p * lg2a(p);
            #pragma unroll
            for (int off = 8; off; off >>= 1)
                cpart += __shfl_xor_sync(0x0000ffffu, cpart, off);
            if (tid == 0) C_sm = cpart;
        }
    }
    __syncthreads();

    const float Cc = C_sm;
    const int t  = cblk * TPB + tid;
    const int i0 = 1 + t * IPT;
    float locmin = __int_as_float(0x7f800000);  // +inf

    if (i0 <= NMASK) {
        const int i1 = min(i0 + IPT, NMASK + 1);
        unsigned m = (unsigned)i0 ^ ((unsigned)i0 >> 1);  // 15-bit Gray code

        // ---- init accumulator in shared: acc = b1 + sum_{d in m} c_d ----
        #pragma unroll
        for (int h = 0; h < H64; ++h) {
            float a = b1_sm[h];
            #pragma unroll
            for (int d = 0; d < D16; ++d) {
                float bd = ((m >> d) & 1u) ? 1.f : 0.f;   // hoisted by compiler
                a = fmaf(bd, c_sm[h * D16 + d], a);
            }
            acc_sm[h * TPB + tid] = a;
        }

        float s = 0.f;
        int dd = 0;
        for (int i = i0; i < i1; ++i) {
            if (i != i0) {
                dd = __ffs(i) - 1;          // Gray transition bit
                m ^= (1u << dd);
                s = ((m >> dd) & 1u) ? 1.f : -1.f;
            }

            unsigned long long o2[D16];
            #pragma unroll
            for (int j = 0; j < D16; ++j) o2[j] = 0ull;

            // ---- fused Gray update + dual second layer (packed f32x2) ----
            #pragma unroll
            for (int hb = 0; hb < H64 / 4; ++hb) {
                const float4 Tv = reinterpret_cast<const float4*>(T_sm)[hb];
                #pragma unroll
                for (int k = 0; k < 4; ++k) {
                    const int h = hb * 4 + k;
                    float a = fmaf(s, c_sm[h * D16 + dd], acc_sm[h * TPB + tid]);
                    acc_sm[h * TPB + tid] = a;
                    float tt = (k == 0) ? Tv.x : (k == 1) ? Tv.y : (k == 2) ? Tv.z : Tv.w;
                    float ra = fmaxf(a, 0.f);
                    float rb = fmaxf(tt - a, 0.f);
                    unsigned long long rab = pk2(ra, rb);
                    const ulonglong2* wrow = reinterpret_cast<const ulonglong2*>(&w2p_sm[h * D16]);
                    #pragma unroll
                    for (int jj = 0; jj < 8; ++jj) {
                        ulonglong2 wv = wrow[jj];
                        o2[2 * jj]     = ffma2(rab, wv.x, o2[2 * jj]);
                        o2[2 * jj + 1] = ffma2(rab, wv.y, o2[2 * jj + 1]);
                    }
                }
            }

            // ---- dual softmax (exponentials overwrite o2 in place) ----
            float Sa = 0.f, Sb = 0.f;
            #pragma unroll
            for (int j = 0; j < D16; ++j) {
                float za, zb;
                upk2(o2[j], za, zb);
                float bl = b2L_sm[j];
                float e1 = ex2f(fmaf(za, L2E, bl));
                float e2 = ex2f(fmaf(zb, L2E, bl));
                o2[j] = pk2(e1, e2);
                Sa += e1; Sb += e2;
            }
            float ha  = 0.5f * rcpf(Sa);
            float hb2 = 0.5f * rcpf(Sb);
            float klq = 0.f;
            #pragma unroll
            for (int j = 0; j < D16; ++j) {
                float e1, e2;
                upk2(o2[j], e1, e2);
                float q = fmaf(e1, ha, e2 * hb2);
                q = fmaxf(q, EPSQ);
                klq = fmaf(p_sm[j], lg2a(q), klq);
            }
            locmin = fminf(locmin, Cc - klq);
        }
    }

    // ---- block min-reduce + global atomic ----
    #pragma unroll
    for (int off = 16; off; off >>= 1)
        locmin = fminf(locmin, __shfl_xor_sync(0xffffffffu, locmin, off));
    if ((tid & 31) == 0) wmin_sm[tid >> 5] = locmin;
    __syncthreads();
    if (tid == 0) {
        float v = wmin_sm[0];
        #pragma unroll
        for (int w = 1; w < TPB / 32; ++w) v = fminf(v, wmin_sm[w]);
        atomicMin(&g_min[pair], fmap(v));
    }
}

extern "C" void kernel_launch(void* const* d_in, const int* in_sizes, int n_in,
                              void* d_out, int out_size) {
    const float* state = (const float*)d_in[0];
    const float* cw1 = (const float*)d_in[1];
    const float* cb1 = (const float*)d_in[2];
    const float* cw2 = (const float*)d_in[3];
    const float* cb2 = (const float*)d_in[4];
    const float* ew1 = (const float*)d_in[5];
    const float* eb1 = (const float*)d_in[6];
    const float* ew2 = (const float*)d_in[7];
    const float* eb2 = (const float*)d_in[8];
    float* out = (float*)d_out;

    init_kernel<<<1, 32>>>();
    phi_kernel<<<NPAIR * BLK_PER_PAIR, TPB>>>(state, cw1, cb1, cw2, cb2,
                                              ew1, eb1, ew2, eb2);
    finish_kernel<<<1, 32>>>(out);
}